// round 11
// baseline (speedup 1.0000x reference)
#include <cuda_runtime.h>

#define BB 64
#define CC 512
#define HH 28
#define WW 28
#define HWSZ (HH*WW)
#define HID 32
#define NPLANE (BB*CC)
#define NLAYERS 4
#define QPP 196            // float4 quads per plane
#define PPB 8              // planes per block (1 warp each)
#define NUP (NPLANE/PPB)   // 4096 producer blocks
#define PBPB 64            // producer blocks per batch

// Scratch (static device memory -- allocation-free)
__device__ float g_buf[(size_t)NPLANE * HWSZ];   // ping-pong x buffer (~103MB)
__device__ float g_seq[NPLANE];                  // pooled means [B,C]
__device__ float g_H[2][NPLANE];                 // LSTM hidden (double-buffered)
__device__ float g_C[2][NPLANE];                 // LSTM cell
__device__ float g_GI[2][BB * 3 * CC];           // input-path gates
__device__ float g_GH2[2][3 * CC];               // 2nd-cell hidden gates (row 0)
__device__ int   g_cnt[4][BB * 8];               // per-(slot,batch) arrival counters

__device__ __forceinline__ float sigmf(float x) { return 1.0f / (1.0f + __expf(-x)); }
__device__ __forceinline__ float tanhfast(float x) {
    float e = __expf(2.0f * x);
    return __fdividef(e - 1.0f, e + 1.0f);
}

// ================= cell for one batch (one block, 256 threads) =================
// Phase A (no wait): hidden-path GEMV + gh dots (depends only on prev kernel).
// Then spin until this batch's 64 producer blocks have published seq, then
// input path + gates + state update; batch 0 also the second cell's hidden path.
__device__ __forceinline__ void cell_block(int b, int ws, int zeroState, int slot,
        float* sm,   // >= 1600 floats of shared
        const float* __restrict__ w_ih_l1, const float* __restrict__ b_ih_l1,
        const float* __restrict__ w_ih_l2, const float* __restrict__ b_ih_l2,
        const float* __restrict__ w_hh_l1, const float* __restrict__ b_hh_l1,
        const float* __restrict__ w_hh_l2, const float* __restrict__ b_hh_l2) {
    float* sin0 = sm;            // 512
    float* sin1 = sm + 512;      // 512
    float* hi   = sm + 1024;     // 32
    float* hh   = sm + 1056;     // 32
    float* snh  = sm + 1088;     // 512
    int tid = threadIdx.x, lane = tid & 31, w = tid >> 5;  // 8 warps
    int rsC = 1 - ws;

    // ---- phase A ----
    if (tid < 128) {
        float4 hv = zeroState ? make_float4(0.f, 0.f, 0.f, 0.f)
                              : ((const float4*)(g_H[rsC] + b * CC))[tid];
        ((float4*)sin1)[tid] = hv;
    }
    __syncthreads();
    #pragma unroll
    for (int t = 0; t < 4; t++) {
        int k = t * 8 + w;
        const float4* wr4 = (const float4*)(w_hh_l1 + k * CC);
        float s = 0.f;
        #pragma unroll
        for (int j = lane; j < 128; j += 32) {
            float4 wv = wr4[j], iv = ((const float4*)sin1)[j];
            s += iv.x * wv.x + iv.y * wv.y + iv.z * wv.z + iv.w * wv.w;
        }
        #pragma unroll
        for (int o = 16; o; o >>= 1) s += __shfl_down_sync(0xffffffffu, s, o);
        if (lane == 0) hh[k] = fmaxf(s + b_hh_l1[k], 0.f);
    }
    __syncthreads();

    float ghr[2][3], cxr[2];
    #pragma unroll
    for (int ch = 0; ch < 2; ch++) {
        int c = tid + ch * 256;
        cxr[ch] = zeroState ? 0.f : g_C[rsC][b * CC + c];
        #pragma unroll
        for (int g = 0; g < 3; g++) {
            float acc = b_hh_l2[g * CC + c];
            const float4* wh4 = (const float4*)&w_hh_l2[(g * CC + c) * HID];
            #pragma unroll
            for (int q = 0; q < 8; q++) {
                float4 wh = wh4[q];
                int k = q * 4;
                acc += hh[k]*wh.x + hh[k+1]*wh.y + hh[k+2]*wh.z + hh[k+3]*wh.w;
            }
            ghr[ch][g] = acc;
        }
    }

    // ---- wait for producers of this batch ----
    if (tid == 0) {
        int* cnt = &g_cnt[slot][b * 8];
        while (atomicAdd(cnt, 0) < PBPB) __nanosleep(64);
        atomicExch(cnt, 0);          // sole consumer resets (replay-safe)
        __threadfence();
    }
    __syncthreads();
    if (tid < 128) ((float4*)sin0)[tid] = __ldcg(((const float4*)(g_seq + b * CC)) + tid);
    __syncthreads();

    // ---- phase B: input path ----
    #pragma unroll
    for (int t = 0; t < 4; t++) {
        int k = t * 8 + w;
        const float4* wr4 = (const float4*)(w_ih_l1 + k * CC);
        float s = 0.f;
        #pragma unroll
        for (int j = lane; j < 128; j += 32) {
            float4 wv = wr4[j], iv = ((const float4*)sin0)[j];
            s += iv.x * wv.x + iv.y * wv.y + iv.z * wv.z + iv.w * wv.w;
        }
        #pragma unroll
        for (int o = 16; o; o >>= 1) s += __shfl_down_sync(0xffffffffu, s, o);
        if (lane == 0) hi[k] = fmaxf(s + b_ih_l1[k], 0.f);
    }
    __syncthreads();

    #pragma unroll
    for (int ch = 0; ch < 2; ch++) {
        int c = tid + ch * 256;
        float gi[3];
        #pragma unroll
        for (int g = 0; g < 3; g++) {
            float acc = b_ih_l2[g * CC + c];
            const float4* wi4 = (const float4*)&w_ih_l2[(g * CC + c) * HID];
            #pragma unroll
            for (int q = 0; q < 8; q++) {
                float4 wi = wi4[q];
                int k = q * 4;
                acc += hi[k]*wi.x + hi[k+1]*wi.y + hi[k+2]*wi.z + hi[k+3]*wi.w;
            }
            gi[g] = acc;
            g_GI[ws][(b * 3 + g) * CC + c] = acc;
        }
        float ig = sigmf(gi[0] + ghr[ch][0]);
        float fg = sigmf(gi[1] + ghr[ch][1]);
        float cg = tanhfast(gi[2] + ghr[ch][2]);
        float nc = fg * cxr[ch] + ig * cg;
        float nh = sigmf(nc);
        g_C[ws][b * CC + c] = nc;
        g_H[ws][b * CC + c] = nh;
        snh[c] = nh;
    }

    // ---- batch-0 tail: gh2 from fresh ht[0] ----
    if (b == 0) {
        __syncthreads();
        #pragma unroll
        for (int t = 0; t < 4; t++) {
            int k = t * 8 + w;
            const float4* wr4 = (const float4*)(w_hh_l1 + k * CC);
            float s = 0.f;
            #pragma unroll
            for (int j = lane; j < 128; j += 32) {
                float4 wv = wr4[j], iv = ((const float4*)snh)[j];
                s += iv.x * wv.x + iv.y * wv.y + iv.z * wv.z + iv.w * wv.w;
            }
            #pragma unroll
            for (int o = 16; o; o >>= 1) s += __shfl_down_sync(0xffffffffu, s, o);
            if (lane == 0) hh[k] = fmaxf(s + b_hh_l1[k], 0.f);
        }
        __syncthreads();
        #pragma unroll
        for (int j = tid; j < 3 * CC; j += 256) {
            float acc = b_hh_l2[j];
            const float4* wh4 = (const float4*)&w_hh_l2[j * HID];
            #pragma unroll
            for (int q = 0; q < 8; q++) {
                float4 wh = wh4[q];
                int k = q * 4;
                acc += hh[k]*wh.x + hh[k+1]*wh.y + hh[k+2]*wh.z + hh[k+3]*wh.w;
            }
            g_GH2[ws][j] = acc;
        }
    }
}

// ================= fused kernel =================
// doCell: blocks 0..63 run cell_{next}; producers are blocks 64.. .
// doPool: producers compute plane means only. Otherwise full update stencil.
__global__ void __launch_bounds__(256, 4) k_fused(
        const float* __restrict__ xin, float* __restrict__ xout,
        const float* __restrict__ dw, int rs, int ws2, int zeroState,
        int slot, int doCell, int doPool,
        const float* __restrict__ w_ih_l1, const float* __restrict__ b_ih_l1,
        const float* __restrict__ w_ih_l2, const float* __restrict__ b_ih_l2,
        const float* __restrict__ w_hh_l1, const float* __restrict__ b_hh_l1,
        const float* __restrict__ w_hh_l2, const float* __restrict__ b_hh_l2) {
    __shared__ __align__(16) float sm[PPB * HWSZ + 8];
    int cellOff = doCell ? BB : 0;

    if (doCell && blockIdx.x < BB) {
        cell_block(blockIdx.x, ws2, zeroState, slot, sm,
                   w_ih_l1, b_ih_l1, w_ih_l2, b_ih_l2,
                   w_hh_l1, b_hh_l1, w_hh_l2, b_hh_l2);
        return;
    }
    int pb = blockIdx.x - cellOff;
    int lane = threadIdx.x & 31, w = threadIdx.x >> 5;
    int plane = pb * PPB + w;
    int b = plane >> 9, c = plane & 511;

    if (doPool) {
        const float4* in4 = (const float4*)(xin + (size_t)plane * HWSZ);
        float s = 0.f;
        #pragma unroll
        for (int q = lane; q < QPP; q += 32) {
            float4 v = in4[q];
            s += v.x + v.y + v.z + v.w;
        }
        #pragma unroll
        for (int o = 16; o; o >>= 1) s += __shfl_down_sync(0xffffffffu, s, o);
        if (lane == 0) g_seq[plane] = s * (1.0f / HWSZ);
        __syncthreads();
        if (threadIdx.x == 0) {
            __threadfence();
            atomicAdd(&g_cnt[slot][(pb >> 6) * 8], 1);
        }
        return;
    }

    float* sp = sm + w * HWSZ;
    const float4* in4 = (const float4*)(xin + (size_t)plane * HWSZ);
    float4* sp4 = (float4*)sp;
    #pragma unroll
    for (int q = lane; q < QPP; q += 32) sp4[q] = in4[q];

    // second-cell scale, lane-parallel gate loads (written by PREVIOUS kernel)
    float tg = 0.f;
    if (lane < 3) tg = g_GI[rs][(b * 3 + lane) * CC + c] + g_GH2[rs][lane * CC + c];
    else if (lane == 3) tg = g_C[rs][c];
    float i2  = __shfl_sync(0xffffffffu, tg, 0);
    float f2  = __shfl_sync(0xffffffffu, tg, 1);
    float c2  = __shfl_sync(0xffffffffu, tg, 2);
    float ct0 = __shfl_sync(0xffffffffu, tg, 3);
    float scale = 1.0f + sigmf(sigmf(f2) * ct0 + sigmf(i2) * tanhfast(c2));

    float wq[9];
    const float* wp = dw + c * 9;
    #pragma unroll
    for (int q = 0; q < 9; q++) wq[q] = wp[q];
    __syncwarp();

    int x = lane;
    bool active = x < WW;
    int xi = active ? x : 0;
    bool notL = (x > 0), notR = (x < WW - 1);

    float aL = 0, aC = 0, aR = 0, bL, bC, bR, cL, cC, cR;
    bC = sp[xi];
    bL = __shfl_up_sync(0xffffffffu, bC, 1);   if (!notL) bL = 0;
    bR = __shfl_down_sync(0xffffffffu, bC, 1); if (!notR) bR = 0;
    cC = sp[WW + xi];
    cL = __shfl_up_sync(0xffffffffu, cC, 1);   if (!notL) cL = 0;
    cR = __shfl_down_sync(0xffffffffu, cC, 1); if (!notR) cR = 0;

    float* outp = xout + (size_t)plane * HWSZ;
    float sum = 0.f;
    #pragma unroll
    for (int y = 0; y < HH; y++) {
        float conv = wq[0] * aL + wq[1] * aC + wq[2] * aR
                   + wq[3] * bL + wq[4] * bC + wq[5] * bR
                   + wq[6] * cL + wq[7] * cC + wq[8] * cR;
        float o = fmaf(bC, scale, conv);
        if (active) { outp[y * WW + x] = o; sum += o; }
        aL = bL; aC = bC; aR = bR;
        bL = cL; bC = cC; bR = cR;
        if (y + 2 < HH) {
            cC = sp[(y + 2) * WW + xi];
            cL = __shfl_up_sync(0xffffffffu, cC, 1);   if (!notL) cL = 0;
            cR = __shfl_down_sync(0xffffffffu, cC, 1); if (!notR) cR = 0;
        } else { cC = cL = cR = 0.f; }
    }
    if (doCell) {
        #pragma unroll
        for (int o2 = 16; o2; o2 >>= 1) sum += __shfl_down_sync(0xffffffffu, sum, o2);
        if (lane == 0) g_seq[plane] = sum * (1.0f / HWSZ);
        __syncthreads();
        if (threadIdx.x == 0) {
            __threadfence();
            atomicAdd(&g_cnt[slot][(pb >> 6) * 8], 1);
        }
    }
}

extern "C" void kernel_launch(void* const* d_in, const int* in_sizes, int n_in,
                              void* d_out, int out_size) {
    const float* x        = (const float*)d_in[0];
    const float* w_ih_l1  = (const float*)d_in[1];
    const float* b_ih_l1  = (const float*)d_in[2];
    const float* w_ih_l2  = (const float*)d_in[3];
    const float* b_ih_l2  = (const float*)d_in[4];
    const float* w_hh_l1  = (const float*)d_in[5];
    const float* b_hh_l1  = (const float*)d_in[6];
    const float* w_hh_l2  = (const float*)d_in[7];
    const float* b_hh_l2  = (const float*)d_in[8];
    const float* dw       = (const float*)d_in[9];
    float* out = (float*)d_out;

    float* buf = nullptr;
    cudaGetSymbolAddress((void**)&buf, g_buf);

    // kernel 1: pool producers + cell_0 (writes parity 0), counters slot 0
    k_fused<<<BB + NUP, 256>>>(x, nullptr, dw, /*rs*/0, /*ws2*/0, /*zero*/1,
                               /*slot*/0, /*doCell*/1, /*doPool*/1,
                               w_ih_l1, b_ih_l1, w_ih_l2, b_ih_l2,
                               w_hh_l1, b_hh_l1, w_hh_l2, b_hh_l2);

    const float* cur = x;
    for (int l = 0; l < NLAYERS; l++) {
        int doCell = (l < NLAYERS - 1) ? 1 : 0;
        float* nxt = ((l & 1) == 0) ? buf : out;   // l0->buf, l1->out, l2->buf, l3->out
        int grid = NUP + (doCell ? BB : 0);
        k_fused<<<grid, 256>>>(cur, nxt, dw, /*rs*/l & 1, /*ws2*/(l + 1) & 1,
                               /*zero*/0, /*slot*/l + 1, doCell, /*doPool*/0,
                               w_ih_l1, b_ih_l1, w_ih_l2, b_ih_l2,
                               w_hh_l1, b_hh_l1, w_hh_l2, b_hh_l2);
        cur = nxt;
    }
}

// round 12
// speedup vs baseline: 1.0413x; 1.0413x over previous
#include <cuda_runtime.h>

#define BB 64
#define CC 512
#define HH 28
#define WW 28
#define HWSZ (HH*WW)
#define HID 32
#define NPLANE (BB*CC)
#define NLAYERS 4
#define QPP 196            // float4 quads per plane
#define PPB 8              // planes per block (1 warp each)
#define NUP (NPLANE/PPB)   // 4096 update blocks
#define NCH 128            // channels per phase-2 block
#define SWF 4224           // floats per staged matrix: 128 rows * 33 (padded)
#define CELL_DSMEM (6 * SWF * 4)

// Scratch (static device memory -- allocation-free)
__device__ float g_buf[(size_t)NPLANE * HWSZ];   // ping-pong x buffer (~103MB)
__device__ float g_seq[NPLANE];                  // pooled means [B,C]
__device__ float g_H[2][NPLANE];                 // LSTM hidden (double-buffered)
__device__ float g_C[2][NPLANE];                 // LSTM cell
__device__ float g_GI[2][BB * 3 * CC];           // input-path gates
__device__ float g_GH2[2][3 * CC];               // 2nd-cell hidden gates (row 0)
__device__ float g_hid[BB][64];                  // bottleneck activations [hi|hh]
__device__ int   g_flag[NLAYERS][BB];            // GEMV-done flags
__device__ int   g_dep[NLAYERS][BB];             // phase2 departure counters
__device__ int   g_arr0[NLAYERS], g_dep0[NLAYERS]; // batch-0 tail rendezvous

__device__ __forceinline__ float sigmf(float x) { return 1.0f / (1.0f + __expf(-x)); }
__device__ __forceinline__ float tanhfast(float x) {
    float e = __expf(2.0f * x);
    return __fdividef(e - 1.0f, e + 1.0f);
}

// ---------------- pool: warp-per-plane mean of x ----------------
__global__ void __launch_bounds__(256) k_pool(const float* __restrict__ x) {
    int lane = threadIdx.x & 31, w = threadIdx.x >> 5;
    int plane = blockIdx.x * PPB + w;
    const float4* in4 = (const float4*)(x + (size_t)plane * HWSZ);
    float s = 0.f;
    #pragma unroll
    for (int q = lane; q < QPP; q += 32) {
        float4 v = in4[q];
        s += v.x + v.y + v.z + v.w;
    }
    #pragma unroll
    for (int o = 16; o; o >>= 1) s += __shfl_down_sync(0xffffffffu, s, o);
    if (lane == 0) g_seq[plane] = s * (1.0f / HWSZ);
}

// ---------------- cell: specialized blocks ----------------
// Blocks 0..63: GEMV for batch b -> publish g_hid[b] + flag.
// Blocks 64..319: phase-2 for (batch, 128-channel chunk). Stage weights into
// smem (coalesced, padded) BEFORE waiting on the flag, then cheap smem math.
__global__ void __launch_bounds__(256) k_cell(int layer, int ws, int zeroState,
        const float* __restrict__ w_ih_l1, const float* __restrict__ b_ih_l1,
        const float* __restrict__ w_ih_l2, const float* __restrict__ b_ih_l2,
        const float* __restrict__ w_hh_l1, const float* __restrict__ b_hh_l1,
        const float* __restrict__ w_hh_l2, const float* __restrict__ b_hh_l2) {
    extern __shared__ __align__(16) float sw[];   // 6 * SWF floats (phase2 only)
    __shared__ __align__(16) float sin01[2 * CC]; // GEMV inputs
    __shared__ __align__(16) float shid[64];
    __shared__ __align__(16) float sht[CC];
    __shared__ float sh2[HID];
    int tid = threadIdx.x, lane = tid & 31, w = tid >> 5;   // 8 warps
    int rs = 1 - ws;

    if (blockIdx.x < BB) {
        // ================= GEMV block =================
        int b = blockIdx.x;
        float* sin0 = sin01;
        float* sin1 = sin01 + CC;
        if (tid < 128) {
            ((float4*)sin0)[tid] = ((const float4*)(g_seq + b * CC))[tid];
        } else {
            float4 hv = zeroState ? make_float4(0.f, 0.f, 0.f, 0.f)
                                  : ((const float4*)(g_H[rs] + b * CC))[tid - 128];
            ((float4*)sin1)[tid - 128] = hv;
        }
        __syncthreads();
        #pragma unroll
        for (int t = 0; t < 8; t++) {
            int d = t * 8 + w;
            int path = d >> 5, k = d & 31;
            const float4* wr4 = (const float4*)((path ? w_hh_l1 : w_ih_l1) + k * CC);
            const float4* in4 = (const float4*)(path ? sin1 : sin0);
            float s = 0.f;
            #pragma unroll
            for (int j = lane; j < 128; j += 32) {
                float4 wv = wr4[j], iv = in4[j];
                s += iv.x * wv.x + iv.y * wv.y + iv.z * wv.z + iv.w * wv.w;
            }
            #pragma unroll
            for (int o = 16; o; o >>= 1) s += __shfl_down_sync(0xffffffffu, s, o);
            if (lane == 0) {
                g_hid[b][d] = fmaxf(s + (path ? b_hh_l1 : b_ih_l1)[k], 0.f);
                __threadfence();
            }
        }
        __syncthreads();
        if (tid == 0) atomicExch(&g_flag[layer][b], 1);
        return;
    }

    // ================= phase-2 block =================
    int pb = blockIdx.x - BB;
    int b = pb >> 2, sub = pb & 3;
    int c0 = sub * NCH;

    // stage 6 weight matrices [128 x 32] -> smem rows padded to 33 (conflict-free)
    #pragma unroll
    for (int m = 0; m < 6; m++) {
        const float* src = (m < 3) ? (w_ih_l2 + (m * CC + c0) * HID)
                                   : (w_hh_l2 + ((m - 3) * CC + c0) * HID);
        const float4* src4 = (const float4*)src;
        float* dstm = sw + m * SWF;
        #pragma unroll
        for (int i = 0; i < 4; i++) {
            int idx4 = tid + i * 256;
            float4 v = src4[idx4];
            float* d = dstm + (idx4 >> 3) * 33 + (idx4 & 7) * 4;
            d[0] = v.x; d[1] = v.y; d[2] = v.z; d[3] = v.w;
        }
    }

    int ch = tid >> 1, ks = (tid & 1) * 16;
    int c = c0 + ch;
    float cx = zeroState ? 0.f : g_C[rs][b * CC + c];
    float bi[3], bh[3];
    #pragma unroll
    for (int g = 0; g < 3; g++) { bi[g] = b_ih_l2[g * CC + c]; bh[g] = b_hh_l2[g * CC + c]; }

    // wait for GEMV block
    if (tid == 0) {
        while (atomicAdd(&g_flag[layer][b], 0) == 0) __nanosleep(32);
    }
    __syncthreads();
    if (tid < 16) ((float4*)shid)[tid] = __ldcg(((const float4*)g_hid[b]) + tid);
    __syncthreads();
    if (tid == 0) {   // departure: 4th resets flag+counter (replay-safe)
        int d = atomicAdd(&g_dep[layer][b], 1);
        if (d == 3) { atomicExch(&g_flag[layer][b], 0); atomicExch(&g_dep[layer][b], 0); }
    }

    // gates: 6 dots of 16 from smem (conflict-free), pairwise shfl combine
    float gi[3], gh[3];
    #pragma unroll
    for (int g = 0; g < 3; g++) {
        const float* wi = sw + g * SWF + ch * 33 + ks;
        const float* wh = sw + (3 + g) * SWF + ch * 33 + ks;
        float si = 0.f, sh = 0.f;
        #pragma unroll
        for (int k = 0; k < 16; k++) {
            si += wi[k] * shid[ks + k];
            sh += wh[k] * shid[32 + ks + k];
        }
        gi[g] = si; gh[g] = sh;
    }
    #pragma unroll
    for (int g = 0; g < 3; g++) {
        gi[g] += __shfl_xor_sync(0xffffffffu, gi[g], 1);
        gh[g] += __shfl_xor_sync(0xffffffffu, gh[g], 1);
    }
    if ((tid & 1) == 0) {
        #pragma unroll
        for (int g = 0; g < 3; g++) {
            gi[g] += bi[g]; gh[g] += bh[g];
            g_GI[ws][(b * 3 + g) * CC + c] = gi[g];
        }
        float ig = sigmf(gi[0] + gh[0]);
        float fg = sigmf(gi[1] + gh[1]);
        float cg = tanhfast(gi[2] + gh[2]);
        float nc = fg * cx + ig * cg;
        g_C[ws][b * CC + c] = nc;
        g_H[ws][b * CC + c] = sigmf(nc);
    }

    // batch-0 tail: all 4 chunks rendezvous, then each computes its gh2 slice
    if (b == 0) {
        __threadfence();
        __syncthreads();
        if (tid == 0) {
            atomicAdd(&g_arr0[layer], 1);
            while (atomicAdd(&g_arr0[layer], 0) < 4) __nanosleep(32);
        }
        __syncthreads();
        if (tid < 128) ((float4*)sht)[tid] = __ldcg(((const float4*)g_H[ws]) + tid);
        __syncthreads();
        // hid2 = relu(W1h ht[0] + b1h): 32 dots of 512
        #pragma unroll
        for (int t = 0; t < 4; t++) {
            int k = t * 8 + w;
            const float4* wr4 = (const float4*)(w_hh_l1 + k * CC);
            float s = 0.f;
            #pragma unroll
            for (int j = lane; j < 128; j += 32) {
                float4 wv = wr4[j], iv = ((const float4*)sht)[j];
                s += iv.x * wv.x + iv.y * wv.y + iv.z * wv.z + iv.w * wv.w;
            }
            #pragma unroll
            for (int o = 16; o; o >>= 1) s += __shfl_down_sync(0xffffffffu, s, o);
            if (lane == 0) sh2[k] = fmaxf(s + b_hh_l1[k], 0.f);
        }
        __syncthreads();
        // gh2 slice from already-staged smem weights
        float t3[3];
        #pragma unroll
        for (int g = 0; g < 3; g++) {
            const float* wh = sw + (3 + g) * SWF + ch * 33 + ks;
            float s = 0.f;
            #pragma unroll
            for (int k = 0; k < 16; k++) s += wh[k] * sh2[ks + k];
            t3[g] = s;
        }
        #pragma unroll
        for (int g = 0; g < 3; g++) t3[g] += __shfl_xor_sync(0xffffffffu, t3[g], 1);
        if ((tid & 1) == 0) {
            #pragma unroll
            for (int g = 0; g < 3; g++) g_GH2[ws][g * CC + c] = t3[g] + bh[g];
        }
        if (tid == 0) {
            int d = atomicAdd(&g_dep0[layer], 1);
            if (d == 3) { atomicExch(&g_arr0[layer], 0); atomicExch(&g_dep0[layer], 0); }
        }
    }
}

// ---------------- update: warp-per-plane rolling stencil ----------------
__global__ void __launch_bounds__(256) k_update(
        const float* __restrict__ xin, float* __restrict__ xout,
        const float* __restrict__ dw, int rs, int writeSeq) {
    __shared__ __align__(16) float s[PPB * HWSZ + 4];
    int lane = threadIdx.x & 31, w = threadIdx.x >> 5;
    int plane = blockIdx.x * PPB + w;
    int b = plane >> 9, c = plane & 511;
    float* sp = s + w * HWSZ;

    const float4* in4 = (const float4*)(xin + (size_t)plane * HWSZ);
    float4* sp4 = (float4*)sp;
    #pragma unroll
    for (int q = lane; q < QPP; q += 32) sp4[q] = in4[q];

    float tg = 0.f;
    if (lane < 3) tg = g_GI[rs][(b * 3 + lane) * CC + c] + g_GH2[rs][lane * CC + c];
    else if (lane == 3) tg = g_C[rs][c];
    float i2  = __shfl_sync(0xffffffffu, tg, 0);
    float f2  = __shfl_sync(0xffffffffu, tg, 1);
    float c2  = __shfl_sync(0xffffffffu, tg, 2);
    float ct0 = __shfl_sync(0xffffffffu, tg, 3);
    float scale = 1.0f + sigmf(sigmf(f2) * ct0 + sigmf(i2) * tanhfast(c2));

    float wq[9];
    const float* wp = dw + c * 9;
    #pragma unroll
    for (int q = 0; q < 9; q++) wq[q] = wp[q];
    __syncwarp();

    int x = lane;
    bool active = x < WW;
    int xi = active ? x : 0;
    bool notL = (x > 0), notR = (x < WW - 1);

    float aL = 0, aC = 0, aR = 0, bL, bC, bR, cL, cC, cR;
    bC = sp[xi];
    bL = __shfl_up_sync(0xffffffffu, bC, 1);   if (!notL) bL = 0;
    bR = __shfl_down_sync(0xffffffffu, bC, 1); if (!notR) bR = 0;
    cC = sp[WW + xi];
    cL = __shfl_up_sync(0xffffffffu, cC, 1);   if (!notL) cL = 0;
    cR = __shfl_down_sync(0xffffffffu, cC, 1); if (!notR) cR = 0;

    float* outp = xout + (size_t)plane * HWSZ;
    float sum = 0.f;
    #pragma unroll
    for (int y = 0; y < HH; y++) {
        float conv = wq[0] * aL + wq[1] * aC + wq[2] * aR
                   + wq[3] * bL + wq[4] * bC + wq[5] * bR
                   + wq[6] * cL + wq[7] * cC + wq[8] * cR;
        float o = fmaf(bC, scale, conv);
        if (active) { outp[y * WW + x] = o; sum += o; }
        aL = bL; aC = bC; aR = bR;
        bL = cL; bC = cC; bR = cR;
        if (y + 2 < HH) {
            cC = sp[(y + 2) * WW + xi];
            cL = __shfl_up_sync(0xffffffffu, cC, 1);   if (!notL) cL = 0;
            cR = __shfl_down_sync(0xffffffffu, cC, 1); if (!notR) cR = 0;
        } else { cC = cL = cR = 0.f; }
    }
    if (writeSeq) {
        #pragma unroll
        for (int o2 = 16; o2; o2 >>= 1) sum += __shfl_down_sync(0xffffffffu, sum, o2);
        if (lane == 0) g_seq[plane] = sum * (1.0f / HWSZ);
    }
}

extern "C" void kernel_launch(void* const* d_in, const int* in_sizes, int n_in,
                              void* d_out, int out_size) {
    const float* x        = (const float*)d_in[0];
    const float* w_ih_l1  = (const float*)d_in[1];
    const float* b_ih_l1  = (const float*)d_in[2];
    const float* w_ih_l2  = (const float*)d_in[3];
    const float* b_ih_l2  = (const float*)d_in[4];
    const float* w_hh_l1  = (const float*)d_in[5];
    const float* b_hh_l1  = (const float*)d_in[6];
    const float* w_hh_l2  = (const float*)d_in[7];
    const float* b_hh_l2  = (const float*)d_in[8];
    const float* dw       = (const float*)d_in[9];
    float* out = (float*)d_out;

    float* buf = nullptr;
    cudaGetSymbolAddress((void**)&buf, g_buf);
    cudaFuncSetAttribute(k_cell, cudaFuncAttributeMaxDynamicSharedMemorySize, CELL_DSMEM);

    k_pool<<<NUP, 256>>>(x);

    const float* cur = x;
    for (int l = 0; l < NLAYERS; l++) {
        int ws = l & 1;
        int zero = (l == 0) ? 1 : 0;
        k_cell<<<BB + BB * 4, 256, CELL_DSMEM>>>(l, ws, zero,
                                   w_ih_l1, b_ih_l1, w_ih_l2, b_ih_l2,
                                   w_hh_l1, b_hh_l1, w_hh_l2, b_hh_l2);
        float* nxt = ((l & 1) == 0) ? buf : out;   // l0->buf, l1->out, l2->buf, l3->out
        int writeSeq = (l < NLAYERS - 1) ? 1 : 0;
        k_update<<<NUP, 256>>>(cur, nxt, dw, ws, writeSeq);
        cur = nxt;
    }
}